// round 3
// baseline (speedup 1.0000x reference)
#include <cuda_runtime.h>

#define NMAX 10000
#define EMAX 320000
#define H1 4
#define C 128
#define F1 (H1*C)   // 512

// ---------------- scratch (static __device__, no allocation) ----------------
__device__ int   g_is64;
__device__ int   g_deg[NMAX];
__device__ int   g_off[NMAX + 1];
__device__ int   g_cur[NMAX];
__device__ int   g_csr[EMAX + NMAX];
__device__ float g_h1[NMAX * F1];     // layer1 linear features [N,4,128]
__device__ float g_as1[NMAX * H1];
__device__ float g_ad1[NMAX * H1];
__device__ float g_out1[NMAX * F1];   // relu(gat1 out) [N,512]
__device__ float g_h2[NMAX * C];      // layer2 linear features [N,128]
__device__ float g_as2[NMAX];
__device__ float g_ad2[NMAX];

__device__ __forceinline__ float lrelu(float v) { return v > 0.f ? v : 0.2f * v; }

__device__ __forceinline__ int load_idx(const int* ei32, int pos) {
    // if int64 layout: value i lives at words [2i] (lo) and [2i+1] (hi=0)
    return g_is64 ? ei32[2 * pos] : ei32[pos];
}

// ---------------- dtype detection ----------------
__global__ void detect_kernel(const int* __restrict__ ei32) {
    // int64 little-endian nonneg values < 2^31  => all odd words are 0
    int allzero = 1;
    for (int i = 1; i < 128; i += 2)
        if (ei32[i] != 0) { allzero = 0; break; }
    g_is64 = allzero;
}

// ---------------- CSR build ----------------
__global__ void init_deg_kernel(int n) {
    int i = blockIdx.x * blockDim.x + threadIdx.x;
    if (i < n) g_deg[i] = 1;   // self loop
}

__global__ void count_kernel(const int* __restrict__ ei32, int e) {
    int i = blockIdx.x * blockDim.x + threadIdx.x;
    if (i < e) {
        int dst = load_idx(ei32, e + i);
        atomicAdd(&g_deg[dst], 1);
    }
}

__global__ void scan_kernel(int n) {
    __shared__ int part[1024];
    int t = threadIdx.x;
    int items = (n + 1023) / 1024;
    int start = t * items;
    int local = 0;
    for (int i = 0; i < items; i++) {
        int idx = start + i;
        if (idx < n) local += g_deg[idx];
    }
    part[t] = local;
    __syncthreads();
    for (int off = 1; off < 1024; off <<= 1) {
        int v = (t >= off) ? part[t - off] : 0;
        __syncthreads();
        part[t] += v;
        __syncthreads();
    }
    int run = (t == 0) ? 0 : part[t - 1];
    for (int i = 0; i < items; i++) {
        int idx = start + i;
        if (idx < n) {
            g_off[idx] = run;
            g_cur[idx] = run + 1;   // slot 0 reserved for self loop
            g_csr[run] = idx;       // self loop src
            run += g_deg[idx];
        }
    }
    if (t == 1023) g_off[n] = part[1023];
}

__global__ void scatter_kernel(const int* __restrict__ ei32, int e) {
    int i = blockIdx.x * blockDim.x + threadIdx.x;
    if (i < e) {
        int src = load_idx(ei32, i);
        int dst = load_idx(ei32, e + i);
        int pos = atomicAdd(&g_cur[dst], 1);
        g_csr[pos] = src;
    }
}

// ---------------- layer 1: linear + per-node attention halves ----------------
__global__ void feat1_kernel(const float* __restrict__ x, const float* __restrict__ W1,
                             const float* __restrict__ asw, const float* __restrict__ adw) {
    int node = blockIdx.x;
    int t = threadIdx.x;   // channel 0..127
    __shared__ float sred[128];
    float x0 = x[node * 2 + 0];
    float x1 = x[node * 2 + 1];
    float hv[H1];
#pragma unroll
    for (int h = 0; h < H1; h++) {
        int j = h * C + t;
        hv[h] = x0 * W1[j] + x1 * W1[F1 + j];
        g_h1[node * F1 + j] = hv[h];
    }
#pragma unroll
    for (int h = 0; h < H1; h++) {
        sred[t] = hv[h] * asw[h * C + t];
        __syncthreads();
        for (int s = 64; s > 0; s >>= 1) { if (t < s) sred[t] += sred[t + s]; __syncthreads(); }
        if (t == 0) g_as1[node * H1 + h] = sred[0];
        __syncthreads();
        sred[t] = hv[h] * adw[h * C + t];
        __syncthreads();
        for (int s = 64; s > 0; s >>= 1) { if (t < s) sred[t] += sred[t + s]; __syncthreads(); }
        if (t == 0) g_ad1[node * H1 + h] = sred[0];
        __syncthreads();
    }
}

// ---------------- layer 1: segment softmax + aggregation (block per dst node) ----------------
__global__ void gat1_kernel(const float* __restrict__ b1) {
    int node = blockIdx.x;
    int t = threadIdx.x;   // 512 threads: head = t>>7, channel = t&127
    __shared__ int   s_src[128];
    __shared__ float s_p[128 * H1];
    __shared__ float sred[512];
    __shared__ float s_max[H1];
    __shared__ float s_sum[H1];

    int rs = g_off[node];
    int deg = g_off[node + 1] - rs;

    float adv[H1];
#pragma unroll
    for (int h = 0; h < H1; h++) adv[h] = g_ad1[node * H1 + h];

    // ---- max pass ----
    float lm[H1];
#pragma unroll
    for (int h = 0; h < H1; h++) lm[h] = -1e30f;
    for (int j = t; j < deg; j += 512) {
        int src = g_csr[rs + j];
#pragma unroll
        for (int h = 0; h < H1; h++) {
            float e = lrelu(g_as1[src * H1 + h] + adv[h]);
            lm[h] = fmaxf(lm[h], e);
        }
    }
#pragma unroll
    for (int h = 0; h < H1; h++) {
        sred[t] = lm[h];
        __syncthreads();
        for (int s = 256; s > 0; s >>= 1) { if (t < s) sred[t] = fmaxf(sred[t], sred[t + s]); __syncthreads(); }
        if (t == 0) s_max[h] = sred[0];
        __syncthreads();
    }

    // ---- exp / sum / aggregate (chunked) ----
    float acc = 0.f;
    int hh = t >> 7;
    float psum[H1] = {0.f, 0.f, 0.f, 0.f};   // only threads t<128 contribute
    for (int base = 0; base < deg; base += 128) {
        int cnt = min(128, deg - base);
        if (t < cnt) {
            int src = g_csr[rs + base + t];
            s_src[t] = src;
#pragma unroll
            for (int h = 0; h < H1; h++) {
                float e = lrelu(g_as1[src * H1 + h] + adv[h]);
                float p = __expf(e - s_max[h]);
                s_p[t * H1 + h] = p;
                psum[h] += p;
            }
        }
        __syncthreads();
#pragma unroll 4
        for (int j = 0; j < cnt; j++) {
            acc += s_p[j * H1 + hh] * g_h1[s_src[j] * F1 + t];
        }
        __syncthreads();
    }
#pragma unroll
    for (int h = 0; h < H1; h++) {
        sred[t] = (t < 128) ? psum[h] : 0.f;
        __syncthreads();
        for (int s = 256; s > 0; s >>= 1) { if (t < s) sred[t] += sred[t + s]; __syncthreads(); }
        if (t == 0) s_sum[h] = sred[0];
        __syncthreads();
    }
    float o = acc / (s_sum[hh] + 1e-16f) + b1[t];
    g_out1[node * F1 + t] = fmaxf(o, 0.f);
}

// ---------------- layer 2 GEMM: h2 = out1 @ W2  (512 -> 128) ----------------
__global__ void gemm2_kernel(const float* __restrict__ W2, int n) {
    const int NB = 16;
    int t = threadIdx.x;             // output channel
    int base = blockIdx.x * NB;
    __shared__ float sh[NB * F1];    // 32 KB
    for (int idx = t; idx < NB * F1; idx += 128) {
        int m = idx >> 9, k = idx & 511;
        int node = base + m;
        sh[idx] = (node < n) ? g_out1[node * F1 + k] : 0.f;
    }
    __syncthreads();
    float acc[NB];
#pragma unroll
    for (int m = 0; m < NB; m++) acc[m] = 0.f;
    for (int k = 0; k < F1; k++) {
        float w = W2[k * C + t];
#pragma unroll
        for (int m = 0; m < NB; m++) acc[m] += sh[m * F1 + k] * w;
    }
#pragma unroll
    for (int m = 0; m < NB; m++) {
        int node = base + m;
        if (node < n) g_h2[node * C + t] = acc[m];
    }
}

// ---------------- layer 2 attention halves ----------------
__global__ void attn2_kernel(const float* __restrict__ asw, const float* __restrict__ adw) {
    int node = blockIdx.x;
    int t = threadIdx.x;
    __shared__ float sred[128];
    float h = g_h2[node * C + t];
    sred[t] = h * asw[t];
    __syncthreads();
    for (int s = 64; s > 0; s >>= 1) { if (t < s) sred[t] += sred[t + s]; __syncthreads(); }
    if (t == 0) g_as2[node] = sred[0];
    __syncthreads();
    sred[t] = h * adw[t];
    __syncthreads();
    for (int s = 64; s > 0; s >>= 1) { if (t < s) sred[t] += sred[t + s]; __syncthreads(); }
    if (t == 0) g_ad2[node] = sred[0];
}

// ---------------- layer 2: softmax + aggregation + final projection ----------------
__global__ void gat2_kernel(const float* __restrict__ b2, const float* __restrict__ Wp,
                            const float* __restrict__ bp, float* __restrict__ out) {
    int node = blockIdx.x;
    int t = threadIdx.x;   // channel
    __shared__ int   s_src[128];
    __shared__ float s_p[128];
    __shared__ float sred[128];
    __shared__ float s_stat[2];

    int rs = g_off[node];
    int deg = g_off[node + 1] - rs;
    float ad = g_ad2[node];

    float lm = -1e30f;
    for (int j = t; j < deg; j += 128) {
        int src = g_csr[rs + j];
        lm = fmaxf(lm, lrelu(g_as2[src] + ad));
    }
    sred[t] = lm;
    __syncthreads();
    for (int s = 64; s > 0; s >>= 1) { if (t < s) sred[t] = fmaxf(sred[t], sred[t + s]); __syncthreads(); }
    if (t == 0) s_stat[0] = sred[0];
    __syncthreads();
    float emax = s_stat[0];

    float acc = 0.f, psum = 0.f;
    for (int base = 0; base < deg; base += 128) {
        int cnt = min(128, deg - base);
        if (t < cnt) {
            int src = g_csr[rs + base + t];
            s_src[t] = src;
            float p = __expf(lrelu(g_as2[src] + ad) - emax);
            s_p[t] = p;
            psum += p;
        }
        __syncthreads();
#pragma unroll 4
        for (int j = 0; j < cnt; j++) acc += s_p[j] * g_h2[s_src[j] * C + t];
        __syncthreads();
    }
    sred[t] = psum;
    __syncthreads();
    for (int s = 64; s > 0; s >>= 1) { if (t < s) sred[t] += sred[t + s]; __syncthreads(); }
    if (t == 0) s_stat[1] = sred[0];
    __syncthreads();

    float o = fmaxf(acc / (s_stat[1] + 1e-16f) + b2[t], 0.f);

    sred[t] = o * Wp[t];
    __syncthreads();
    for (int s = 64; s > 0; s >>= 1) { if (t < s) sred[t] += sred[t + s]; __syncthreads(); }
    if (t == 0) out[node] = sred[0] + bp[0];
}

// ---------------- launch ----------------
extern "C" void kernel_launch(void* const* d_in, const int* in_sizes, int n_in,
                              void* d_out, int out_size) {
    const float* x    = (const float*)d_in[0];
    const int*   ei32 = (const int*)d_in[1];    // int32 OR int64 (detected on device)
    const float* W1   = (const float*)d_in[2];
    const float* as1w = (const float*)d_in[3];
    const float* ad1w = (const float*)d_in[4];
    const float* b1   = (const float*)d_in[5];
    const float* W2   = (const float*)d_in[6];
    const float* as2w = (const float*)d_in[7];
    const float* ad2w = (const float*)d_in[8];
    const float* b2   = (const float*)d_in[9];
    const float* Wp   = (const float*)d_in[10];
    const float* bp   = (const float*)d_in[11];
    float* out = (float*)d_out;

    int n = in_sizes[0] / 2;   // x is [N,2]
    int e = in_sizes[1] / 2;   // edge_index is [2,E] (element count is 2E for both dtypes)

    detect_kernel<<<1, 1>>>(ei32);
    init_deg_kernel<<<(n + 255) / 256, 256>>>(n);
    count_kernel<<<(e + 255) / 256, 256>>>(ei32, e);
    scan_kernel<<<1, 1024>>>(n);
    scatter_kernel<<<(e + 255) / 256, 256>>>(ei32, e);

    feat1_kernel<<<n, 128>>>(x, W1, as1w, ad1w);
    gat1_kernel<<<n, 512>>>(b1);

    gemm2_kernel<<<(n + 15) / 16, 128>>>(W2, n);
    attn2_kernel<<<n, 128>>>(as2w, ad2w);
    gat2_kernel<<<n, 128>>>(b2, Wp, bp, out);
}

// round 4
// speedup vs baseline: 2.2297x; 2.2297x over previous
#include <cuda_runtime.h>

#define NMAX 10000
#define EMAX 320000
#define H1 4
#define C 128
#define F1 (H1*C)   // 512

// ---------------- scratch (static __device__, no allocation) ----------------
__device__ int   g_is64;
__device__ int   g_deg[NMAX];
__device__ int   g_off[NMAX + 1];
__device__ int   g_cur[NMAX];
__device__ int   g_csr[EMAX + NMAX];
__device__ __align__(16) float g_h1[NMAX * F1];     // [N,4,128]
__device__ __align__(16) float g_as1[NMAX * H1];
__device__ __align__(16) float g_ad1[NMAX * H1];
__device__ __align__(16) float g_out1[NMAX * F1];   // relu(gat1 out) [N,512]
__device__ __align__(16) float g_h2[NMAX * C];      // [N,128]
__device__ float g_as2[NMAX];
__device__ float g_ad2[NMAX];

__device__ __forceinline__ float lrelu(float v) { return v > 0.f ? v : 0.2f * v; }

__device__ __forceinline__ int load_idx(const int* ei32, int pos) {
    return g_is64 ? ei32[2 * pos] : ei32[pos];
}

// ---------------- init: self-loop degree + dtype detect ----------------
__global__ void init_kernel(const int* __restrict__ ei32, int n) {
    int i = blockIdx.x * blockDim.x + threadIdx.x;
    if (i < n) g_deg[i] = 1;
    if (i == 0) {
        // int64 little-endian nonneg small values => all odd 32-bit words are 0
        int allzero = 1;
        for (int k = 1; k < 128; k += 2)
            if (ei32[k] != 0) { allzero = 0; break; }
        g_is64 = allzero;
    }
}

__global__ void count_kernel(const int* __restrict__ ei32, int e) {
    int i = blockIdx.x * blockDim.x + threadIdx.x;
    if (i < e) atomicAdd(&g_deg[load_idx(ei32, e + i)], 1);
}

// ---------------- shuffle-based single-block scan ----------------
__global__ void scan_kernel(int n) {
    int t = threadIdx.x;                 // 1024 threads
    int items = (n + 1023) >> 10;        // <=16 for n<=16384
    int start = t * items;
    int d[16];
    int local = 0;
    for (int i = 0; i < items; i++) {
        int idx = start + i;
        int v = (idx < n) ? g_deg[idx] : 0;
        d[i] = v; local += v;
    }
    unsigned full = 0xFFFFFFFFu;
    int lane = t & 31, w = t >> 5;
    int inc = local;
#pragma unroll
    for (int o = 1; o < 32; o <<= 1) {
        int v = __shfl_up_sync(full, inc, o);
        if (lane >= o) inc += v;
    }
    __shared__ int warptot[32];
    if (lane == 31) warptot[w] = inc;
    __syncthreads();
    if (w == 0) {
        int v = warptot[lane];
        int inc2 = v;
#pragma unroll
        for (int o = 1; o < 32; o <<= 1) {
            int x = __shfl_up_sync(full, inc2, o);
            if (lane >= o) inc2 += x;
        }
        warptot[lane] = inc2;
    }
    __syncthreads();
    int run = inc - local + ((w > 0) ? warptot[w - 1] : 0);
    for (int i = 0; i < items; i++) {
        int idx = start + i;
        if (idx < n) {
            g_off[idx] = run;
            g_cur[idx] = run + 1;   // slot 0 = self loop
            g_csr[run] = idx;
            run += d[i];
        }
    }
    if (t == 1023) g_off[n] = run;
}

__global__ void scatter_kernel(const int* __restrict__ ei32, int e) {
    int i = blockIdx.x * blockDim.x + threadIdx.x;
    if (i < e) {
        int src = load_idx(ei32, i);
        int dst = load_idx(ei32, e + i);
        int pos = atomicAdd(&g_cur[dst], 1);
        g_csr[pos] = src;
    }
}

// ---------------- layer 1: linear + attention halves (shuffle reduce) ----------------
__global__ void feat1_kernel(const float* __restrict__ x, const float* __restrict__ W1,
                             const float* __restrict__ asw, const float* __restrict__ adw) {
    int node = blockIdx.x;
    int t = threadIdx.x;                 // 128
    int lane = t & 31, w = t >> 5;
    float x0 = x[node * 2 + 0];
    float x1 = x[node * 2 + 1];
    float dots[8];
#pragma unroll
    for (int h = 0; h < H1; h++) {
        int j = h * C + t;
        float hv = x0 * W1[j] + x1 * W1[F1 + j];
        g_h1[node * F1 + j] = hv;
        dots[2 * h]     = hv * asw[j];
        dots[2 * h + 1] = hv * adw[j];
    }
#pragma unroll
    for (int k = 0; k < 8; k++)
#pragma unroll
        for (int o = 16; o > 0; o >>= 1)
            dots[k] += __shfl_down_sync(0xFFFFFFFFu, dots[k], o);
    __shared__ float s[4][8];
    if (lane == 0) {
#pragma unroll
        for (int k = 0; k < 8; k++) s[w][k] = dots[k];
    }
    __syncthreads();
    if (t < 8) {
        float v = s[0][t] + s[1][t] + s[2][t] + s[3][t];
        int h = t >> 1;
        if (t & 1) g_ad1[node * H1 + h] = v;
        else       g_as1[node * H1 + h] = v;
    }
}

// ---------------- layer 1: softmax + aggregation, float4, 128 threads ----------------
__global__ void gat1_kernel(const float* __restrict__ b1) {
    int node = blockIdx.x;
    int t = threadIdx.x;                 // channel quad: channels 4t..4t+3, head = t>>5
    int h = t >> 5;
    __shared__ int    s_src[128];
    __shared__ float4 s_p[128];
    __shared__ float4 sred4[128];
    __shared__ float4 s_maxv;
    __shared__ float4 s_sumv;

    int rs = g_off[node];
    int deg = g_off[node + 1] - rs;

    const float4* as1 = (const float4*)g_as1;
    float4 adv = ((const float4*)g_ad1)[node];

    // ---- max pass ----
    float4 lm = make_float4(-1e30f, -1e30f, -1e30f, -1e30f);
    for (int j = t; j < deg; j += 128) {
        int src = g_csr[rs + j];
        float4 av = as1[src];
        lm.x = fmaxf(lm.x, lrelu(av.x + adv.x));
        lm.y = fmaxf(lm.y, lrelu(av.y + adv.y));
        lm.z = fmaxf(lm.z, lrelu(av.z + adv.z));
        lm.w = fmaxf(lm.w, lrelu(av.w + adv.w));
    }
    sred4[t] = lm;
    __syncthreads();
    for (int s = 64; s > 0; s >>= 1) {
        if (t < s) {
            float4 a = sred4[t], b = sred4[t + s];
            a.x = fmaxf(a.x, b.x); a.y = fmaxf(a.y, b.y);
            a.z = fmaxf(a.z, b.z); a.w = fmaxf(a.w, b.w);
            sred4[t] = a;
        }
        __syncthreads();
    }
    if (t == 0) s_maxv = sred4[0];
    __syncthreads();
    float4 mx = s_maxv;

    // ---- exp / sum / aggregate (chunks of 128 edges) ----
    float4 acc  = make_float4(0.f, 0.f, 0.f, 0.f);
    float4 psum = make_float4(0.f, 0.f, 0.f, 0.f);
    const float4* h1 = (const float4*)g_h1;
    for (int base = 0; base < deg; base += 128) {
        int cnt = min(128, deg - base);
        if (t < cnt) {
            int src = g_csr[rs + base + t];
            s_src[t] = src;
            float4 av = as1[src];
            float4 p;
            p.x = __expf(lrelu(av.x + adv.x) - mx.x);
            p.y = __expf(lrelu(av.y + adv.y) - mx.y);
            p.z = __expf(lrelu(av.z + adv.z) - mx.z);
            p.w = __expf(lrelu(av.w + adv.w) - mx.w);
            s_p[t] = p;
            psum.x += p.x; psum.y += p.y; psum.z += p.z; psum.w += p.w;
        }
        __syncthreads();
#pragma unroll 4
        for (int j = 0; j < cnt; j++) {
            int src = s_src[j];
            float4 v = h1[src * 128 + t];
            float pj = ((const float*)(s_p + j))[h];
            acc.x += pj * v.x; acc.y += pj * v.y;
            acc.z += pj * v.z; acc.w += pj * v.w;
        }
        __syncthreads();
    }
    sred4[t] = psum;
    __syncthreads();
    for (int s = 64; s > 0; s >>= 1) {
        if (t < s) {
            float4 a = sred4[t], b = sred4[t + s];
            a.x += b.x; a.y += b.y; a.z += b.z; a.w += b.w;
            sred4[t] = a;
        }
        __syncthreads();
    }
    if (t == 0) s_sumv = sred4[0];
    __syncthreads();
    float inv = 1.f / (((const float*)&s_sumv)[h] + 1e-16f);

    float4 bq = ((const float4*)b1)[t];
    float4 o;
    o.x = fmaxf(acc.x * inv + bq.x, 0.f);
    o.y = fmaxf(acc.y * inv + bq.y, 0.f);
    o.z = fmaxf(acc.z * inv + bq.z, 0.f);
    o.w = fmaxf(acc.w * inv + bq.w, 0.f);
    ((float4*)g_out1)[node * 128 + t] = o;
}

// ---------------- layer 2 GEMM (512->128) + fused attention dots ----------------
__global__ void gemm2_kernel(const float* __restrict__ W2,
                             const float* __restrict__ asw, const float* __restrict__ adw,
                             int n) {
    const int NB = 16;
    int t = threadIdx.x;                 // output channel
    int base = blockIdx.x * NB;
    __shared__ float4 sh[NB * 128];      // 32 KB
    const float4* o1 = (const float4*)g_out1;
    for (int idx = t; idx < NB * 128; idx += 128) {
        int m = idx >> 7, q = idx & 127;
        int node = base + m;
        sh[idx] = (node < n) ? o1[node * 128 + q] : make_float4(0.f, 0.f, 0.f, 0.f);
    }
    __syncthreads();
    float acc[NB];
#pragma unroll
    for (int m = 0; m < NB; m++) acc[m] = 0.f;
    for (int k = 0; k < F1; k += 4) {
        float w0 = W2[(k + 0) * C + t];
        float w1 = W2[(k + 1) * C + t];
        float w2 = W2[(k + 2) * C + t];
        float w3 = W2[(k + 3) * C + t];
#pragma unroll
        for (int m = 0; m < NB; m++) {
            float4 s = sh[m * 128 + (k >> 2)];
            acc[m] += s.x * w0 + s.y * w1 + s.z * w2 + s.w * w3;
        }
    }
    // write h2 + fused attn2 dots via warp shuffles
    float a_s = asw[t], a_d = adw[t];
    __shared__ float s_as[4][NB], s_ad[4][NB];
    int w = t >> 5, lane = t & 31;
#pragma unroll
    for (int m = 0; m < NB; m++) {
        int node = base + m;
        if (node < n) g_h2[node * C + t] = acc[m];
        float vs = acc[m] * a_s, vd = acc[m] * a_d;
#pragma unroll
        for (int o = 16; o > 0; o >>= 1) {
            vs += __shfl_down_sync(0xFFFFFFFFu, vs, o);
            vd += __shfl_down_sync(0xFFFFFFFFu, vd, o);
        }
        if (lane == 0) { s_as[w][m] = vs; s_ad[w][m] = vd; }
    }
    __syncthreads();
    if (t < NB) {
        int node = base + t;
        if (node < n) {
            g_as2[node] = s_as[0][t] + s_as[1][t] + s_as[2][t] + s_as[3][t];
            g_ad2[node] = s_ad[0][t] + s_ad[1][t] + s_ad[2][t] + s_ad[3][t];
        }
    }
}

// ---------------- layer 2: softmax + aggregation + projection, float4 ----------------
__global__ void gat2_kernel(const float* __restrict__ b2, const float* __restrict__ Wp,
                            const float* __restrict__ bp, float* __restrict__ out) {
    int node = blockIdx.x;
    int t = threadIdx.x;                 // 128
    int g = t >> 5, q = t & 31;          // edge subgroup g, channel quad q
    __shared__ int    s_src[128];
    __shared__ float  s_p[128];
    __shared__ float  sred[128];
    __shared__ float4 s_acc[4][32];

    int rs = g_off[node];
    int deg = g_off[node + 1] - rs;
    float ad = g_ad2[node];

    float lm = -1e30f;
    for (int j = t; j < deg; j += 128)
        lm = fmaxf(lm, lrelu(g_as2[g_csr[rs + j]] + ad));
    sred[t] = lm;
    __syncthreads();
    for (int s = 64; s > 0; s >>= 1) {
        if (t < s) sred[t] = fmaxf(sred[t], sred[t + s]);
        __syncthreads();
    }
    float emax = sred[0];

    float4 acc = make_float4(0.f, 0.f, 0.f, 0.f);
    float psum = 0.f;
    const float4* h2 = (const float4*)g_h2;
    for (int base = 0; base < deg; base += 128) {
        int cnt = min(128, deg - base);
        if (t < cnt) {
            int src = g_csr[rs + base + t];
            s_src[t] = src;
            float p = __expf(lrelu(g_as2[src] + ad) - emax);
            s_p[t] = p;
            psum += p;
        }
        __syncthreads();
#pragma unroll 2
        for (int j = g; j < cnt; j += 4) {
            float4 v = h2[s_src[j] * 32 + q];
            float pj = s_p[j];
            acc.x += pj * v.x; acc.y += pj * v.y;
            acc.z += pj * v.z; acc.w += pj * v.w;
        }
        __syncthreads();
    }
    sred[t] = psum;
    __syncthreads();
    for (int s = 64; s > 0; s >>= 1) {
        if (t < s) sred[t] += sred[t + s];
        __syncthreads();
    }
    float inv = 1.f / (sred[0] + 1e-16f);

    s_acc[g][q] = acc;
    __syncthreads();
    if (t < 32) {
        float4 a = s_acc[0][t], b = s_acc[1][t], c = s_acc[2][t], d = s_acc[3][t];
        a.x += b.x + c.x + d.x; a.y += b.y + c.y + d.y;
        a.z += b.z + c.z + d.z; a.w += b.w + c.w + d.w;
        float4 bq = ((const float4*)b2)[t];
        float4 wq = ((const float4*)Wp)[t];
        float o0 = fmaxf(a.x * inv + bq.x, 0.f);
        float o1 = fmaxf(a.y * inv + bq.y, 0.f);
        float o2 = fmaxf(a.z * inv + bq.z, 0.f);
        float o3 = fmaxf(a.w * inv + bq.w, 0.f);
        float v = o0 * wq.x + o1 * wq.y + o2 * wq.z + o3 * wq.w;
#pragma unroll
        for (int o = 16; o > 0; o >>= 1)
            v += __shfl_down_sync(0xFFFFFFFFu, v, o);
        if (t == 0) out[node] = v + bp[0];
    }
}

// ---------------- launch ----------------
extern "C" void kernel_launch(void* const* d_in, const int* in_sizes, int n_in,
                              void* d_out, int out_size) {
    const float* x    = (const float*)d_in[0];
    const int*   ei32 = (const int*)d_in[1];
    const float* W1   = (const float*)d_in[2];
    const float* as1w = (const float*)d_in[3];
    const float* ad1w = (const float*)d_in[4];
    const float* b1   = (const float*)d_in[5];
    const float* W2   = (const float*)d_in[6];
    const float* as2w = (const float*)d_in[7];
    const float* ad2w = (const float*)d_in[8];
    const float* b2   = (const float*)d_in[9];
    const float* Wp   = (const float*)d_in[10];
    const float* bp   = (const float*)d_in[11];
    float* out = (float*)d_out;

    int n = in_sizes[0] / 2;   // x is [N,2]
    int e = in_sizes[1] / 2;   // edge_index is [2,E]

    init_kernel<<<(n + 255) / 256, 256>>>(ei32, n);
    count_kernel<<<(e + 255) / 256, 256>>>(ei32, e);
    scan_kernel<<<1, 1024>>>(n);
    scatter_kernel<<<(e + 255) / 256, 256>>>(ei32, e);

    feat1_kernel<<<n, 128>>>(x, W1, as1w, ad1w);
    gat1_kernel<<<n, 128>>>(b1);

    gemm2_kernel<<<(n + 15) / 16, 128>>>(W2, as2w, ad2w, n);
    gat2_kernel<<<n, 128>>>(b2, Wp, bp, out);
}

// round 5
// speedup vs baseline: 2.5010x; 1.1216x over previous
#include <cuda_runtime.h>
#include <cuda_fp16.h>

#define NMAX 10000
#define EMAX 320000
#define H1 4
#define C 128
#define F1 (H1*C)   // 512
#define DCAP 512    // cached-softmax capacity (max indegree fast path)

// ---------------- scratch (static __device__, no allocation) ----------------
__device__ int   g_is64;
__device__ int   g_deg[NMAX];
__device__ int   g_off[NMAX + 1];
__device__ int   g_cur[NMAX];
__device__ int   g_csr[EMAX + NMAX];
__device__ __align__(16) __half2 g_h1h[NMAX * (F1 / 2)];  // [N,512] as half2
__device__ __align__(16) float g_as1[NMAX * H1];
__device__ __align__(16) float g_ad1[NMAX * H1];
__device__ __align__(16) float g_out1[NMAX * F1];   // relu(gat1 out) [N,512]
__device__ __align__(16) float g_h2[NMAX * C];      // [N,128]
__device__ float g_as2[NMAX];
__device__ float g_ad2[NMAX];

__device__ __forceinline__ float lrelu(float v) { return v > 0.f ? v : 0.2f * v; }

__device__ __forceinline__ int load_idx(const int* ei32, int pos) {
    return g_is64 ? ei32[2 * pos] : ei32[pos];
}

// ---- packed f32x2 helpers (sm_103a FFMA2 via PTX) ----
__device__ __forceinline__ unsigned long long pack_f2(float lo, float hi) {
    unsigned long long r;
    asm("mov.b64 %0, {%1, %2};" : "=l"(r) : "f"(lo), "f"(hi));
    return r;
}
__device__ __forceinline__ void fma_f32x2(unsigned long long& d,
                                          unsigned long long a, unsigned long long b) {
    asm("fma.rn.f32x2 %0, %1, %2, %3;" : "=l"(d) : "l"(a), "l"(b), "l"(d));
}
__device__ __forceinline__ float2 unpack_f2(unsigned long long v) {
    float lo, hi;
    asm("mov.b64 {%0, %1}, %2;" : "=f"(lo), "=f"(hi) : "l"(v));
    return make_float2(lo, hi);
}

// ---------------- init: self-loop degree + dtype detect ----------------
__global__ void init_kernel(const int* __restrict__ ei32, int n) {
    int i = blockIdx.x * blockDim.x + threadIdx.x;
    if (i < n) g_deg[i] = 1;
    if (i == 0) {
        int allzero = 1;
        for (int k = 1; k < 128; k += 2)
            if (ei32[k] != 0) { allzero = 0; break; }
        g_is64 = allzero;
    }
}

__global__ void count_kernel(const int* __restrict__ ei32, int e) {
    int i = blockIdx.x * blockDim.x + threadIdx.x;
    if (i < e) atomicAdd(&g_deg[load_idx(ei32, e + i)], 1);
}

// ---------------- shuffle-based single-block scan ----------------
__global__ void scan_kernel(int n) {
    int t = threadIdx.x;                 // 1024 threads
    int items = (n + 1023) >> 10;
    int start = t * items;
    int d[16];
    int local = 0;
    for (int i = 0; i < items; i++) {
        int idx = start + i;
        int v = (idx < n) ? g_deg[idx] : 0;
        d[i] = v; local += v;
    }
    unsigned full = 0xFFFFFFFFu;
    int lane = t & 31, w = t >> 5;
    int inc = local;
#pragma unroll
    for (int o = 1; o < 32; o <<= 1) {
        int v = __shfl_up_sync(full, inc, o);
        if (lane >= o) inc += v;
    }
    __shared__ int warptot[32];
    if (lane == 31) warptot[w] = inc;
    __syncthreads();
    if (w == 0) {
        int v = warptot[lane];
        int inc2 = v;
#pragma unroll
        for (int o = 1; o < 32; o <<= 1) {
            int x = __shfl_up_sync(full, inc2, o);
            if (lane >= o) inc2 += x;
        }
        warptot[lane] = inc2;
    }
    __syncthreads();
    int run = inc - local + ((w > 0) ? warptot[w - 1] : 0);
    for (int i = 0; i < items; i++) {
        int idx = start + i;
        if (idx < n) {
            g_off[idx] = run;
            g_cur[idx] = run + 1;   // slot 0 = self loop
            g_csr[run] = idx;
            run += d[i];
        }
    }
    if (t == 1023) g_off[n] = run;
}

__global__ void scatter_kernel(const int* __restrict__ ei32, int e) {
    int i = blockIdx.x * blockDim.x + threadIdx.x;
    if (i < e) {
        int src = load_idx(ei32, i);
        int dst = load_idx(ei32, e + i);
        int pos = atomicAdd(&g_cur[dst], 1);
        g_csr[pos] = src;
    }
}

// ---------------- layer 1: linear + attention halves (no syncs) ----------------
// thread t owns features 4t..4t+3 ; warp w == head w (32 threads * 4 ch = 128)
__global__ void feat1_kernel(const float* __restrict__ x, const float* __restrict__ W1,
                             const float* __restrict__ asw, const float* __restrict__ adw) {
    int node = blockIdx.x;
    int t = threadIdx.x;                 // 128
    int lane = t & 31, w = t >> 5;
    float x0 = x[node * 2 + 0];
    float x1 = x[node * 2 + 1];
    float hv[4];
    float ds = 0.f, dd = 0.f;
#pragma unroll
    for (int i = 0; i < 4; i++) {
        int f = 4 * t + i;
        hv[i] = x0 * W1[f] + x1 * W1[F1 + f];
        ds += hv[i] * asw[f];
        dd += hv[i] * adw[f];
    }
    g_h1h[node * 256 + 2 * t]     = __floats2half2_rn(hv[0], hv[1]);
    g_h1h[node * 256 + 2 * t + 1] = __floats2half2_rn(hv[2], hv[3]);
#pragma unroll
    for (int o = 16; o > 0; o >>= 1) {
        ds += __shfl_down_sync(0xFFFFFFFFu, ds, o);
        dd += __shfl_down_sync(0xFFFFFFFFu, dd, o);
    }
    if (lane == 0) {
        g_as1[node * H1 + w] = ds;
        g_ad1[node * H1 + w] = dd;
    }
}

// ---- float4 block reductions over 128 threads (shuffle + 4-warp combine) ----
__device__ __forceinline__ float4 blk_max4(float4 v, float4* s4, int t) {
    int lane = t & 31, w = t >> 5;
#pragma unroll
    for (int o = 16; o > 0; o >>= 1) {
        v.x = fmaxf(v.x, __shfl_down_sync(0xFFFFFFFFu, v.x, o));
        v.y = fmaxf(v.y, __shfl_down_sync(0xFFFFFFFFu, v.y, o));
        v.z = fmaxf(v.z, __shfl_down_sync(0xFFFFFFFFu, v.z, o));
        v.w = fmaxf(v.w, __shfl_down_sync(0xFFFFFFFFu, v.w, o));
    }
    if (lane == 0) s4[w] = v;
    __syncthreads();
    float4 a = s4[0], b = s4[1], c = s4[2], d = s4[3];
    a.x = fmaxf(fmaxf(a.x, b.x), fmaxf(c.x, d.x));
    a.y = fmaxf(fmaxf(a.y, b.y), fmaxf(c.y, d.y));
    a.z = fmaxf(fmaxf(a.z, b.z), fmaxf(c.z, d.z));
    a.w = fmaxf(fmaxf(a.w, b.w), fmaxf(c.w, d.w));
    return a;
}
__device__ __forceinline__ float4 blk_sum4(float4 v, float4* s4, int t) {
    int lane = t & 31, w = t >> 5;
#pragma unroll
    for (int o = 16; o > 0; o >>= 1) {
        v.x += __shfl_down_sync(0xFFFFFFFFu, v.x, o);
        v.y += __shfl_down_sync(0xFFFFFFFFu, v.y, o);
        v.z += __shfl_down_sync(0xFFFFFFFFu, v.z, o);
        v.w += __shfl_down_sync(0xFFFFFFFFu, v.w, o);
    }
    if (lane == 0) s4[w] = v;
    __syncthreads();
    float4 a = s4[0], b = s4[1], c = s4[2], d = s4[3];
    a.x += b.x + c.x + d.x; a.y += b.y + c.y + d.y;
    a.z += b.z + c.z + d.z; a.w += b.w + c.w + d.w;
    return a;
}

// ---------------- layer 1: cached softmax + fp16 gather aggregation ----------------
__global__ void gat1_kernel(const float* __restrict__ b1) {
    int node = blockIdx.x;
    int t = threadIdx.x;                 // channels 4t..4t+3, head h = t>>5
    int h = t >> 5;
    __shared__ int    s_src[DCAP];
    __shared__ float4 s_p[DCAP];         // e-values, then p-values
    __shared__ float4 s_red[4];

    int rs = g_off[node];
    int deg = g_off[node + 1] - rs;

    const float4* as1 = (const float4*)g_as1;
    float4 adv = ((const float4*)g_ad1)[node];

    float4 acc  = make_float4(0.f, 0.f, 0.f, 0.f);
    float4 psum = make_float4(0.f, 0.f, 0.f, 0.f);
    float4 mx;

    if (deg <= DCAP) {
        // phase A: gather attention scalars once, cache e
        float4 lm = make_float4(-1e30f, -1e30f, -1e30f, -1e30f);
        for (int j = t; j < deg; j += 128) {
            int src = g_csr[rs + j];
            s_src[j] = src;
            float4 av = as1[src];
            float4 e;
            e.x = lrelu(av.x + adv.x); e.y = lrelu(av.y + adv.y);
            e.z = lrelu(av.z + adv.z); e.w = lrelu(av.w + adv.w);
            s_p[j] = e;
            lm.x = fmaxf(lm.x, e.x); lm.y = fmaxf(lm.y, e.y);
            lm.z = fmaxf(lm.z, e.z); lm.w = fmaxf(lm.w, e.w);
        }
        __syncthreads();
        mx = blk_max4(lm, s_red, t);
        __syncthreads();
        // phase B: exp in place
        for (int j = t; j < deg; j += 128) {
            float4 e = s_p[j];
            float4 p;
            p.x = __expf(e.x - mx.x); p.y = __expf(e.y - mx.y);
            p.z = __expf(e.z - mx.z); p.w = __expf(e.w - mx.w);
            s_p[j] = p;
            psum.x += p.x; psum.y += p.y; psum.z += p.z; psum.w += p.w;
        }
        __syncthreads();
        // phase C: fp16 feature gather
        const float* pf = (const float*)s_p;
#pragma unroll 4
        for (int j = 0; j < deg; j++) {
            int src = s_src[j];
            uint2 raw = *reinterpret_cast<const uint2*>(&g_h1h[src * 256 + 2 * t]);
            float2 fa = __half22float2(*reinterpret_cast<__half2*>(&raw.x));
            float2 fb = __half22float2(*reinterpret_cast<__half2*>(&raw.y));
            float pj = pf[j * 4 + h];
            acc.x += pj * fa.x; acc.y += pj * fa.y;
            acc.z += pj * fb.x; acc.w += pj * fb.y;
        }
    } else {
        // fallback: two-pass, chunked (never expected on this graph)
        float4 lm = make_float4(-1e30f, -1e30f, -1e30f, -1e30f);
        for (int j = t; j < deg; j += 128) {
            float4 av = as1[g_csr[rs + j]];
            lm.x = fmaxf(lm.x, lrelu(av.x + adv.x));
            lm.y = fmaxf(lm.y, lrelu(av.y + adv.y));
            lm.z = fmaxf(lm.z, lrelu(av.z + adv.z));
            lm.w = fmaxf(lm.w, lrelu(av.w + adv.w));
        }
        __syncthreads();
        mx = blk_max4(lm, s_red, t);
        for (int base = 0; base < deg; base += DCAP) {
            int cnt = min(DCAP, deg - base);
            __syncthreads();
            for (int j = t; j < cnt; j += 128) {
                int src = g_csr[rs + base + j];
                s_src[j] = src;
                float4 av = as1[src];
                float4 p;
                p.x = __expf(lrelu(av.x + adv.x) - mx.x);
                p.y = __expf(lrelu(av.y + adv.y) - mx.y);
                p.z = __expf(lrelu(av.z + adv.z) - mx.z);
                p.w = __expf(lrelu(av.w + adv.w) - mx.w);
                s_p[j] = p;
                psum.x += p.x; psum.y += p.y; psum.z += p.z; psum.w += p.w;
            }
            __syncthreads();
            const float* pf = (const float*)s_p;
            for (int j = 0; j < cnt; j++) {
                int src = s_src[j];
                uint2 raw = *reinterpret_cast<const uint2*>(&g_h1h[src * 256 + 2 * t]);
                float2 fa = __half22float2(*reinterpret_cast<__half2*>(&raw.x));
                float2 fb = __half22float2(*reinterpret_cast<__half2*>(&raw.y));
                float pj = pf[j * 4 + h];
                acc.x += pj * fa.x; acc.y += pj * fa.y;
                acc.z += pj * fb.x; acc.w += pj * fb.y;
            }
        }
        __syncthreads();
    }

    float4 sum = blk_sum4(psum, s_red, t);
    float inv = 1.f / (((const float*)&sum)[h] + 1e-16f);

    float4 bq = ((const float4*)b1)[t];
    float4 o;
    o.x = fmaxf(acc.x * inv + bq.x, 0.f);
    o.y = fmaxf(acc.y * inv + bq.y, 0.f);
    o.z = fmaxf(acc.z * inv + bq.z, 0.f);
    o.w = fmaxf(acc.w * inv + bq.w, 0.f);
    ((float4*)g_out1)[node * 128 + t] = o;
}

// ---------------- layer 2 GEMM (512->128, FFMA2) + fused attention dots ----------------
__global__ void __launch_bounds__(128) gemm2_kernel(const float* __restrict__ W2,
                             const float* __restrict__ asw, const float* __restrict__ adw,
                             int n) {
    const int NB = 16;
    int t = threadIdx.x;                 // output channel
    int base = blockIdx.x * NB;
    __shared__ float4 sh[NB * 128];      // 32 KB: node-major, k-quads
    const float4* o1 = (const float4*)g_out1;
    for (int idx = t; idx < NB * 128; idx += 128) {
        int m = idx >> 7, q = idx & 127;
        int node = base + m;
        sh[idx] = (node < n) ? o1[node * 128 + q] : make_float4(0.f, 0.f, 0.f, 0.f);
    }
    __syncthreads();
    unsigned long long acc2[NB];
#pragma unroll
    for (int m = 0; m < NB; m++) acc2[m] = pack_f2(0.f, 0.f);
    for (int kq = 0; kq < 128; kq++) {
        int k = kq * 4;
        unsigned long long wp01 = pack_f2(W2[(k + 0) * C + t], W2[(k + 1) * C + t]);
        unsigned long long wp23 = pack_f2(W2[(k + 2) * C + t], W2[(k + 3) * C + t]);
#pragma unroll
        for (int m = 0; m < NB; m++) {
            float4 s = sh[m * 128 + kq];
            fma_f32x2(acc2[m], pack_f2(s.x, s.y), wp01);
            fma_f32x2(acc2[m], pack_f2(s.z, s.w), wp23);
        }
    }
    // finalize h2 + fused attn2 dots
    float a_s = asw[t], a_d = adw[t];
    __shared__ float s_as[4][NB], s_ad[4][NB];
    int w = t >> 5, lane = t & 31;
#pragma unroll
    for (int m = 0; m < NB; m++) {
        float2 pr = unpack_f2(acc2[m]);
        float hv = pr.x + pr.y;
        int node = base + m;
        if (node < n) g_h2[node * C + t] = hv;
        float vs = hv * a_s, vd = hv * a_d;
#pragma unroll
        for (int o = 16; o > 0; o >>= 1) {
            vs += __shfl_down_sync(0xFFFFFFFFu, vs, o);
            vd += __shfl_down_sync(0xFFFFFFFFu, vd, o);
        }
        if (lane == 0) { s_as[w][m] = vs; s_ad[w][m] = vd; }
    }
    __syncthreads();
    if (t < NB) {
        int node = base + t;
        if (node < n) {
            g_as2[node] = s_as[0][t] + s_as[1][t] + s_as[2][t] + s_as[3][t];
            g_ad2[node] = s_ad[0][t] + s_ad[1][t] + s_ad[2][t] + s_ad[3][t];
        }
    }
}

// ---------------- layer 2: cached softmax + aggregation + projection ----------------
__global__ void gat2_kernel(const float* __restrict__ b2, const float* __restrict__ Wp,
                            const float* __restrict__ bp, float* __restrict__ out) {
    int node = blockIdx.x;
    int t = threadIdx.x;                 // 128
    int g = t >> 5, q = t & 31;          // edge subgroup g, channel quad q
    __shared__ int    s_src[DCAP];
    __shared__ float  s_p[DCAP];
    __shared__ float  sred[4];
    __shared__ float4 s_acc[4][32];

    int rs = g_off[node];
    int deg = g_off[node + 1] - rs;
    float ad = g_ad2[node];
    int lane = t & 31, w = t >> 5;

    float4 acc = make_float4(0.f, 0.f, 0.f, 0.f);
    float psum = 0.f;
    float emax;
    const float4* h2 = (const float4*)g_h2;

    if (deg <= DCAP) {
        float lm = -1e30f;
        for (int j = t; j < deg; j += 128) {
            int src = g_csr[rs + j];
            s_src[j] = src;
            float e = lrelu(g_as2[src] + ad);
            s_p[j] = e;
            lm = fmaxf(lm, e);
        }
        __syncthreads();
#pragma unroll
        for (int o = 16; o > 0; o >>= 1) lm = fmaxf(lm, __shfl_down_sync(0xFFFFFFFFu, lm, o));
        if (lane == 0) sred[w] = lm;
        __syncthreads();
        emax = fmaxf(fmaxf(sred[0], sred[1]), fmaxf(sred[2], sred[3]));
        __syncthreads();
        for (int j = t; j < deg; j += 128) {
            float p = __expf(s_p[j] - emax);
            s_p[j] = p;
            psum += p;
        }
        __syncthreads();
#pragma unroll 4
        for (int j = g; j < deg; j += 4) {
            float4 v = h2[s_src[j] * 32 + q];
            float pj = s_p[j];
            acc.x += pj * v.x; acc.y += pj * v.y;
            acc.z += pj * v.z; acc.w += pj * v.w;
        }
    } else {
        float lm = -1e30f;
        for (int j = t; j < deg; j += 128)
            lm = fmaxf(lm, lrelu(g_as2[g_csr[rs + j]] + ad));
#pragma unroll
        for (int o = 16; o > 0; o >>= 1) lm = fmaxf(lm, __shfl_down_sync(0xFFFFFFFFu, lm, o));
        if (lane == 0) sred[w] = lm;
        __syncthreads();
        emax = fmaxf(fmaxf(sred[0], sred[1]), fmaxf(sred[2], sred[3]));
        for (int bas = 0; bas < deg; bas += DCAP) {
            int cnt = min(DCAP, deg - bas);
            __syncthreads();
            for (int j = t; j < cnt; j += 128) {
                int src = g_csr[rs + bas + j];
                s_src[j] = src;
                float p = __expf(lrelu(g_as2[src] + ad) - emax);
                s_p[j] = p;
                psum += p;
            }
            __syncthreads();
            for (int j = g; j < cnt; j += 4) {
                float4 v = h2[s_src[j] * 32 + q];
                float pj = s_p[j];
                acc.x += pj * v.x; acc.y += pj * v.y;
                acc.z += pj * v.z; acc.w += pj * v.w;
            }
        }
        __syncthreads();
    }

    // sum of p over block
    {
        float v = psum;
#pragma unroll
        for (int o = 16; o > 0; o >>= 1) v += __shfl_down_sync(0xFFFFFFFFu, v, o);
        if (lane == 0) sred[w] = v;
    }
    s_acc[g][q] = acc;
    __syncthreads();
    if (t < 32) {
        float inv = 1.f / (sred[0] + sred[1] + sred[2] + sred[3] + 1e-16f);
        float4 a = s_acc[0][t], b = s_acc[1][t], c = s_acc[2][t], d = s_acc[3][t];
        a.x += b.x + c.x + d.x; a.y += b.y + c.y + d.y;
        a.z += b.z + c.z + d.z; a.w += b.w + c.w + d.w;
        float4 bq = ((const float4*)b2)[t];
        float4 wq = ((const float4*)Wp)[t];
        float o0 = fmaxf(a.x * inv + bq.x, 0.f);
        float o1 = fmaxf(a.y * inv + bq.y, 0.f);
        float o2 = fmaxf(a.z * inv + bq.z, 0.f);
        float o3 = fmaxf(a.w * inv + bq.w, 0.f);
        float v = o0 * wq.x + o1 * wq.y + o2 * wq.z + o3 * wq.w;
#pragma unroll
        for (int o = 16; o > 0; o >>= 1)
            v += __shfl_down_sync(0xFFFFFFFFu, v, o);
        if (t == 0) out[node] = v + bp[0];
    }
}

// ---------------- launch ----------------
extern "C" void kernel_launch(void* const* d_in, const int* in_sizes, int n_in,
                              void* d_out, int out_size) {
    const float* x    = (const float*)d_in[0];
    const int*   ei32 = (const int*)d_in[1];
    const float* W1   = (const float*)d_in[2];
    const float* as1w = (const float*)d_in[3];
    const float* ad1w = (const float*)d_in[4];
    const float* b1   = (const float*)d_in[5];
    const float* W2   = (const float*)d_in[6];
    const float* as2w = (const float*)d_in[7];
    const float* ad2w = (const float*)d_in[8];
    const float* b2   = (const float*)d_in[9];
    const float* Wp   = (const float*)d_in[10];
    const float* bp   = (const float*)d_in[11];
    float* out = (float*)d_out;

    int n = in_sizes[0] / 2;   // x is [N,2]
    int e = in_sizes[1] / 2;   // edge_index is [2,E]

    init_kernel<<<(n + 255) / 256, 256>>>(ei32, n);
    count_kernel<<<(e + 255) / 256, 256>>>(ei32, e);
    scan_kernel<<<1, 1024>>>(n);
    scatter_kernel<<<(e + 255) / 256, 256>>>(ei32, e);

    feat1_kernel<<<n, 128>>>(x, W1, as1w, ad1w);
    gat1_kernel<<<n, 128>>>(b1);

    gemm2_kernel<<<(n + 15) / 16, 128>>>(W2, as2w, ad2w, n);
    gat2_kernel<<<n, 128>>>(b2, Wp, bp, out);
}